// round 11
// baseline (speedup 1.0000x reference)
#include <cuda_runtime.h>
#include <math.h>

#define B 64
#define T 4096
#define D 512
#define NSPLIT 32                // CTAs per batch in partial kernel
#define WARPS 4                  // warps per CTA (128 threads)
#define NPART NSPLIT             // ONE partial per CTA (warps merged in smem)
#define ROWS_PER_WARP 32         // (T/NSPLIT)/WARPS

#define KD 32                    // key kernel: d-columns per CTA
#define KB 32                    // key kernel: batches per CTA
#define KZ 4                     // key kernel: split-K factor
#define KSLICE (D / KZ)          // 128 floats per K slice
#define QPITCH 132               // floats; P4=33 odd -> 8 distinct bank-groups

// Scratch (static device globals: allocation-free)
__device__ float g_kpart[KZ * B * D];                // 512 KB (split-K partials)
__device__ float g_pm[B * NPART];
__device__ float g_ps[B * NPART];
__device__ float g_pc[(size_t)B * NPART * D];        // 4.2 MB
__device__ int   g_mask_kind;                        // 0=int32, 1=uint8, 2=float32

// ---------------------------------------------------------------------------
// Kernel 1: split-K key GEMM with 4x W reuse.
// R10 profile: L1=40.4% busy, DRAM=1.7% -> L1-wavefront bound on 4.2M LDG.128.
// Now each thread computes FOUR b-outputs per W fragment: 1 LDG.128 feeds
// 4 LDS.128 + 16 FMA. Global loads drop 4x. Thread's b's are strided by 8
// (b = b0 + bl + 8u) so the 8 distinct smem row addresses per LDS phase hit
// 8 distinct bank-groups (pitch 132 floats, P4=33 odd) -> conflict-free.
// Block (0,0,0) also sniffs the mask dtype (idempotent atomicMax).
// ---------------------------------------------------------------------------
__global__ __launch_bounds__(256) void key_kernel(const float* __restrict__ q,
                                                  const float* __restrict__ W,
                                                  const float* __restrict__ bias,
                                                  const unsigned int* __restrict__ mw) {
    if (blockIdx.x == 0 && blockIdx.y == 0 && blockIdx.z == 0) {
        int kind = 0;
        for (int i = threadIdx.x; i < 2048; i += blockDim.x) {
            unsigned int w = mw[i];
            if (w == 0x3f800000u)            kind = 2;                    // float 1.0f
            else if ((w & 0xFFFFFF00u) != 0) kind = kind > 1 ? kind : 1;  // high byte set
        }
        if (kind) atomicMax(&g_mask_kind, kind);   // stays 0 => int32
    }

    __shared__ float qs[KB * QPITCH];   // 32 q rows x 128-float slice, pitch 132

    const int b0 = blockIdx.y * KB;
    const int d0 = blockIdx.x * KD;
    const int k0 = blockIdx.z * KSLICE;

    // Stage q tile: 32 rows x 32 float4; 256 threads x 4 each (coalesced).
#pragma unroll
    for (int i = 0; i < 4; i++) {
        int idx = threadIdx.x + i * 256;          // 0..1023
        int row = idx >> 5;                       // 32 float4 per row
        int col = idx & 31;
        float4 v = *reinterpret_cast<const float4*>(q + (size_t)(b0 + row) * D + k0 + 4 * col);
        *reinterpret_cast<float4*>(&qs[row * QPITCH + 4 * col]) = v;
    }
    __syncthreads();

    const int warp = threadIdx.x >> 5;
    const int lane = threadIdx.x & 31;
    const int d    = d0 + warp * 4 + (lane >> 3);
    const int bl   = lane & 7;                    // b = b0 + bl + 8u

    const float4* wrow = reinterpret_cast<const float4*>(W + (size_t)d * D + k0);

    float4 acc[4];
#pragma unroll
    for (int u = 0; u < 4; u++) acc[u] = make_float4(0.f, 0.f, 0.f, 0.f);

#pragma unroll
    for (int j = 0; j < KSLICE / 4; j++) {        // 32 iterations
        float4 wv = wrow[j];
#pragma unroll
        for (int u = 0; u < 4; u++) {
            float4 qv = *reinterpret_cast<const float4*>(&qs[(bl + 8 * u) * QPITCH + 4 * j]);
            acc[u].x = fmaf(wv.x, qv.x, acc[u].x);
            acc[u].y = fmaf(wv.y, qv.y, acc[u].y);
            acc[u].z = fmaf(wv.z, qv.z, acc[u].z);
            acc[u].w = fmaf(wv.w, qv.w, acc[u].w);
        }
    }

    const float bd = (blockIdx.z == 0) ? bias[d] : 0.f;
#pragma unroll
    for (int u = 0; u < 4; u++) {
        float r = (acc[u].x + acc[u].y) + (acc[u].z + acc[u].w) + bd;
        g_kpart[blockIdx.z * (B * D) + (size_t)(b0 + bl + 8 * u) * D + d] = r;
    }
}

// ---------------------------------------------------------------------------
// Kernel 2: per-warp online softmax over a 32-row strip, masked rows skipped;
// the 4 warp states are then merged in smem -> ONE partial per CTA. k fragment
// is the sum of the 4 split-K slices (L2-hit loads). A streamed with __ldcs.
// Unroll 8 so ptxas hoists more row-pair loads across the shuffle/exp chains.
// ---------------------------------------------------------------------------
__global__ __launch_bounds__(128) void partial_kernel(const float* __restrict__ A,
                                                      const void* __restrict__ mask_raw) {
    const int b     = blockIdx.x / NSPLIT;
    const int split = blockIdx.x % NSPLIT;
    const int warp  = threadIdx.x >> 5;
    const int lane  = threadIdx.x & 31;
    const int t0    = split * (T / NSPLIT) + warp * ROWS_PER_WARP;

    const size_t midx = (size_t)(t0 + lane) * B + b;
    const int kind = g_mask_kind;
    bool masked;
    if (kind == 1)      masked = ((const unsigned char*)mask_raw)[midx] != 0;
    else if (kind == 0) masked = ((const int*)mask_raw)[midx] != 0;
    else                masked = ((const float*)mask_raw)[midx] != 0.f;
    const unsigned mvote = __ballot_sync(0xffffffffu, masked);

    // k fragment: sum the 4 split-K slices (deterministic order)
    float4 kf[4];
#pragma unroll
    for (int j = 0; j < 4; j++) {
        const float* kb = g_kpart + (size_t)b * D + 4 * lane + 128 * j;
        float4 s = *reinterpret_cast<const float4*>(kb);
#pragma unroll
        for (int z = 1; z < KZ; z++) {
            float4 t = *reinterpret_cast<const float4*>(kb + (size_t)z * B * D);
            s.x += t.x; s.y += t.y; s.z += t.z; s.w += t.w;
        }
        kf[j] = s;
    }

    float mA = -INFINITY, sA = 0.f, mB = -INFINITY, sB = 0.f;
    float4 cA[4], cB[4];
#pragma unroll
    for (int j = 0; j < 4; j++) {
        cA[j] = make_float4(0.f, 0.f, 0.f, 0.f);
        cB[j] = make_float4(0.f, 0.f, 0.f, 0.f);
    }

    const float* base = A + ((size_t)b * T + t0) * D + 4 * lane;

#pragma unroll 8
    for (int rp = 0; rp < ROWS_PER_WARP; rp += 2) {
        const bool doA = !((mvote >> rp) & 1u);       // warp-uniform
        const bool doB = !((mvote >> (rp + 1)) & 1u); // warp-uniform
        float4 aA[4], aB[4];
        const float* rowA = base + (size_t)rp * D;
        const float* rowB = rowA + D;
        if (doA) {
#pragma unroll
            for (int j = 0; j < 4; j++)
                aA[j] = __ldcs(reinterpret_cast<const float4*>(rowA + 128 * j));
        }
        if (doB) {
#pragma unroll
            for (int j = 0; j < 4; j++)
                aB[j] = __ldcs(reinterpret_cast<const float4*>(rowB + 128 * j));
        }

        float pA = 0.f, pB = 0.f;
        if (doA) {
#pragma unroll
            for (int j = 0; j < 4; j++) {
                pA = fmaf(aA[j].x, kf[j].x, pA);
                pA = fmaf(aA[j].y, kf[j].y, pA);
                pA = fmaf(aA[j].z, kf[j].z, pA);
                pA = fmaf(aA[j].w, kf[j].w, pA);
            }
        }
        if (doB) {
#pragma unroll
            for (int j = 0; j < 4; j++) {
                pB = fmaf(aB[j].x, kf[j].x, pB);
                pB = fmaf(aB[j].y, kf[j].y, pB);
                pB = fmaf(aB[j].z, kf[j].z, pB);
                pB = fmaf(aB[j].w, kf[j].w, pB);
            }
        }
#pragma unroll
        for (int off = 16; off > 0; off >>= 1) {
            if (doA) pA += __shfl_xor_sync(0xffffffffu, pA, off);
            if (doB) pB += __shfl_xor_sync(0xffffffffu, pB, off);
        }

        if (doA) {
            float mn    = fmaxf(mA, pA);
            float alpha = __expf(mA - mn);   // mA=-inf -> 0
            float w     = __expf(pA - mn);
            sA = sA * alpha + w;
#pragma unroll
            for (int j = 0; j < 4; j++) {
                cA[j].x = fmaf(w, aA[j].x, cA[j].x * alpha);
                cA[j].y = fmaf(w, aA[j].y, cA[j].y * alpha);
                cA[j].z = fmaf(w, aA[j].z, cA[j].z * alpha);
                cA[j].w = fmaf(w, aA[j].w, cA[j].w * alpha);
            }
            mA = mn;
        }
        if (doB) {
            float mn    = fmaxf(mB, pB);
            float alpha = __expf(mB - mn);
            float w     = __expf(pB - mn);
            sB = sB * alpha + w;
#pragma unroll
            for (int j = 0; j < 4; j++) {
                cB[j].x = fmaf(w, aB[j].x, cB[j].x * alpha);
                cB[j].y = fmaf(w, aB[j].y, cB[j].y * alpha);
                cB[j].z = fmaf(w, aB[j].z, cB[j].z * alpha);
                cB[j].w = fmaf(w, aB[j].w, cB[j].w * alpha);
            }
            mB = mn;
        }
    }

    // merge states A and B within the warp (guard all-masked: both -inf)
    float m = fmaxf(mA, mB), s;
    if (m == -INFINITY) {
        s = 0.f;
#pragma unroll
        for (int j = 0; j < 4; j++) cA[j] = make_float4(0.f, 0.f, 0.f, 0.f);
    } else {
        float eA = (mA == -INFINITY) ? 0.f : __expf(mA - m);
        float eB = (mB == -INFINITY) ? 0.f : __expf(mB - m);
        s = sA * eA + sB * eB;
#pragma unroll
        for (int j = 0; j < 4; j++) {
            cA[j].x = cA[j].x * eA + cB[j].x * eB;
            cA[j].y = cA[j].y * eA + cB[j].y * eB;
            cA[j].z = cA[j].z * eA + cB[j].z * eB;
            cA[j].w = cA[j].w * eA + cB[j].w * eB;
        }
    }

    // ---- CTA-level merge of the 4 warp states (smem) ----
    __shared__ float sm_m[WARPS], sm_s[WARPS];
    __shared__ float sm_c[WARPS][D];
    if (lane == 0) { sm_m[warp] = m; sm_s[warp] = s; }
    __syncthreads();
    const float M = fmaxf(fmaxf(sm_m[0], sm_m[1]), fmaxf(sm_m[2], sm_m[3]));
    const float myscale = (m == -INFINITY) ? 0.f : __expf(m - M);
    float* cw = &sm_c[warp][4 * lane];
#pragma unroll
    for (int j = 0; j < 4; j++) {
        float4 v = cA[j];
        v.x *= myscale; v.y *= myscale; v.z *= myscale; v.w *= myscale;
        *reinterpret_cast<float4*>(cw + 128 * j) = v;
    }
    __syncthreads();

    const int pid = blockIdx.x;   // b*NSPLIT + split
    if (threadIdx.x == 0) {
        float st = 0.f;
#pragma unroll
        for (int w = 0; w < WARPS; w++) {
            float sc = (sm_m[w] == -INFINITY) ? 0.f : __expf(sm_m[w] - M);
            st += sm_s[w] * sc;
        }
        g_pm[pid] = M;
        g_ps[pid] = st;
    }
    float* pc = g_pc + (size_t)pid * D;
#pragma unroll
    for (int j = 0; j < 4; j++) {
        int col = threadIdx.x + 128 * j;
        pc[col] = ((sm_c[0][col] + sm_c[1][col]) + (sm_c[2][col] + sm_c[3][col]));
    }
}

// ---------------------------------------------------------------------------
// Kernel 3: combine 32 partials per batch.  256 CTAs (4 per batch), 128
// threads; each thread owns one of its CTA's 128 D-columns.
// ---------------------------------------------------------------------------
__global__ __launch_bounds__(128) void reduce_kernel(float* __restrict__ out) {
    const int b    = blockIdx.x >> 2;
    const int part = blockIdx.x & 3;
    const int tid  = threadIdx.x;

    __shared__ float sc[NPART];
    __shared__ float Msh, Ssh;

    if (tid < NPART) sc[tid] = g_pm[b * NPART + tid];
    __syncthreads();
    if (tid == 0) {
        float mm = -INFINITY;
#pragma unroll
        for (int i = 0; i < NPART; i++) mm = fmaxf(mm, sc[i]);
        Msh = mm;
    }
    __syncthreads();
    if (tid < NPART) {
        float mi = sc[tid];
        sc[tid] = (mi == -INFINITY) ? 0.f : __expf(mi - Msh);
    }
    __syncthreads();
    if (tid == 0) {
        float acc = 0.f;
#pragma unroll
        for (int i = 0; i < NPART; i++) acc += sc[i] * g_ps[b * NPART + i];
        Ssh = acc;
    }
    __syncthreads();

    const int d = part * 128 + tid;
    float acc = 0.f;
    const float* pc = g_pc + (size_t)b * NPART * D + d;
#pragma unroll
    for (int i = 0; i < NPART; i++)
        acc = fmaf(pc[(size_t)i * D], sc[i], acc);
    out[b * D + d] = acc / Ssh;
}

// ---------------------------------------------------------------------------
extern "C" void kernel_launch(void* const* d_in, const int* in_sizes, int n_in,
                              void* d_out, int out_size) {
    const float* q    = (const float*)d_in[0];   // [B, D]
    const float* A    = (const float*)d_in[1];   // [B, T, D]
    const void*  mask = d_in[2];                 // [T, B] bool-ish (dtype sniffed)
    const float* W    = (const float*)d_in[3];   // [D, D]
    const float* bias = (const float*)d_in[4];   // [D]
    float*       out  = (float*)d_out;           // [B, 1, D]

    key_kernel<<<dim3(D / KD, B / KB, KZ), 256>>>(q, W, bias, (const unsigned int*)mask);
    partial_kernel<<<B * NSPLIT, WARPS * 32>>>(A, mask);
    reduce_kernel<<<B * 4, 128>>>(out);
}

// round 13
// speedup vs baseline: 1.0025x; 1.0025x over previous
#include <cuda_runtime.h>
#include <math.h>

#define B 64
#define T 4096
#define D 512
#define NSPLIT 32                // CTAs per batch in partial kernel
#define WARPS 4                  // warps per CTA (128 threads)
#define NPART NSPLIT             // ONE partial per CTA (warps merged in smem)
#define ROWS_PER_WARP 32         // (T/NSPLIT)/WARPS

#define KD 32                    // key kernel: d-columns per CTA
#define KB 32                    // key kernel: batches per CTA
#define KZ 16                    // key kernel: split-K factor
#define KSLICE (D / KZ)          // 32 floats per K slice
#define QP4 9                    // smem pitch in float4 (odd -> conflict-free)

// Scratch (static device globals: allocation-free)
__device__ float g_kpart[KZ * B * D];                // 2 MB (split-K partials)
__device__ float g_key[B * D];                       // 128 KB (folded key)
__device__ float g_pm[B * NPART];
__device__ float g_ps[B * NPART];
__device__ float g_pc[(size_t)B * NPART * D];        // 4.2 MB
__device__ int   g_mask_kind;                        // 0=int32, 1=uint8, 2=float32

// ---------------------------------------------------------------------------
// Kernel 1: split-K key GEMM with 4x W reuse AND high occupancy.
// R11 lesson: KB=32 with KZ=4 gave only 128 CTAs (occ 12.6%) -> latency-bound.
// Now KZ=16 (KSLICE=32): grid (16,2,16)=512 CTAs, occ ~41% like R10, but with
// R11's 4x-lower LDG count (1M LDG.128). Per thread: 8 independent W float4
// loads + 32 LDS.128 (pitch QP4=9 float4, odd -> lanes bl=0..7 hit 8 distinct
// 16B bank-groups -> conflict-free).
// Block (0,0,0) also sniffs the mask dtype (idempotent atomicMax).
// ---------------------------------------------------------------------------
__global__ __launch_bounds__(256) void key_kernel(const float* __restrict__ q,
                                                  const float* __restrict__ W,
                                                  const float* __restrict__ bias,
                                                  const unsigned int* __restrict__ mw) {
    if (blockIdx.x == 0 && blockIdx.y == 0 && blockIdx.z == 0) {
        int kind = 0;
        for (int i = threadIdx.x; i < 2048; i += blockDim.x) {
            unsigned int w = mw[i];
            if (w == 0x3f800000u)            kind = 2;                    // float 1.0f
            else if ((w & 0xFFFFFF00u) != 0) kind = kind > 1 ? kind : 1;  // high byte set
        }
        if (kind) atomicMax(&g_mask_kind, kind);   // stays 0 => int32
    }

    __shared__ float4 qs[KB * QP4];   // 32 rows x 8 float4 (pitch 9) = 4.6 KB

    const int b0 = blockIdx.y * KB;
    const int d0 = blockIdx.x * KD;
    const int k0 = blockIdx.z * KSLICE;

    // Stage q tile: 32 rows x 8 float4 = 256; exactly one per thread.
    {
        int row = threadIdx.x >> 3;               // 8 float4 per row
        int col = threadIdx.x & 7;
        qs[row * QP4 + col] =
            *reinterpret_cast<const float4*>(q + (size_t)(b0 + row) * D + k0 + 4 * col);
    }
    __syncthreads();

    const int warp = threadIdx.x >> 5;
    const int lane = threadIdx.x & 31;
    const int d    = d0 + warp * 4 + (lane >> 3);
    const int bl   = lane & 7;                    // b = b0 + bl + 8u

    const float4* wrow = reinterpret_cast<const float4*>(W + (size_t)d * D + k0);

    float4 acc[4];
#pragma unroll
    for (int u = 0; u < 4; u++) acc[u] = make_float4(0.f, 0.f, 0.f, 0.f);

#pragma unroll
    for (int j = 0; j < KSLICE / 4; j++) {        // 8 iterations, 8 independent LDGs
        float4 wv = wrow[j];
#pragma unroll
        for (int u = 0; u < 4; u++) {
            float4 qv = qs[(bl + 8 * u) * QP4 + j];
            acc[u].x = fmaf(wv.x, qv.x, acc[u].x);
            acc[u].y = fmaf(wv.y, qv.y, acc[u].y);
            acc[u].z = fmaf(wv.z, qv.z, acc[u].z);
            acc[u].w = fmaf(wv.w, qv.w, acc[u].w);
        }
    }

    const float bd = (blockIdx.z == 0) ? bias[d] : 0.f;
#pragma unroll
    for (int u = 0; u < 4; u++) {
        float r = (acc[u].x + acc[u].y) + (acc[u].z + acc[u].w) + bd;
        g_kpart[blockIdx.z * (B * D) + (size_t)(b0 + bl + 8 * u) * D + d] = r;
    }
}

// ---------------------------------------------------------------------------
// Kernel 1b: fold the KZ split-K slices into g_key ONCE, so partial warps
// load a plain 2KB k-row instead of re-summing 16 slices (kills the 64MB of
// redundant L2 traffic the old in-partial sum generated).
// ---------------------------------------------------------------------------
__global__ __launch_bounds__(256) void fold_kernel() {
    const int i = blockIdx.x * 256 + threadIdx.x;   // 0 .. B*D-1
    float s = 0.f;
#pragma unroll
    for (int z = 0; z < KZ; z++)
        s += g_kpart[z * (B * D) + i];
    g_key[i] = s;
}

// ---------------------------------------------------------------------------
// Kernel 2: per-warp online softmax over a 32-row strip, masked rows skipped;
// the 4 warp states are merged in smem -> ONE partial per CTA. k row comes
// from folded g_key (L2-hit). A streamed with __ldcs.
// ---------------------------------------------------------------------------
__global__ __launch_bounds__(128) void partial_kernel(const float* __restrict__ A,
                                                      const void* __restrict__ mask_raw) {
    const int b     = blockIdx.x / NSPLIT;
    const int split = blockIdx.x % NSPLIT;
    const int warp  = threadIdx.x >> 5;
    const int lane  = threadIdx.x & 31;
    const int t0    = split * (T / NSPLIT) + warp * ROWS_PER_WARP;

    const size_t midx = (size_t)(t0 + lane) * B + b;
    const int kind = g_mask_kind;
    bool masked;
    if (kind == 1)      masked = ((const unsigned char*)mask_raw)[midx] != 0;
    else if (kind == 0) masked = ((const int*)mask_raw)[midx] != 0;
    else                masked = ((const float*)mask_raw)[midx] != 0.f;
    const unsigned mvote = __ballot_sync(0xffffffffu, masked);

    float4 kf[4];
    const float* kb = g_key + b * D + 4 * lane;
#pragma unroll
    for (int j = 0; j < 4; j++)
        kf[j] = *reinterpret_cast<const float4*>(kb + 128 * j);

    float mA = -INFINITY, sA = 0.f, mB = -INFINITY, sB = 0.f;
    float4 cA[4], cB[4];
#pragma unroll
    for (int j = 0; j < 4; j++) {
        cA[j] = make_float4(0.f, 0.f, 0.f, 0.f);
        cB[j] = make_float4(0.f, 0.f, 0.f, 0.f);
    }

    const float* base = A + ((size_t)b * T + t0) * D + 4 * lane;

#pragma unroll 8
    for (int rp = 0; rp < ROWS_PER_WARP; rp += 2) {
        const bool doA = !((mvote >> rp) & 1u);       // warp-uniform
        const bool doB = !((mvote >> (rp + 1)) & 1u); // warp-uniform
        float4 aA[4], aB[4];
        const float* rowA = base + (size_t)rp * D;
        const float* rowB = rowA + D;
        if (doA) {
#pragma unroll
            for (int j = 0; j < 4; j++)
                aA[j] = __ldcs(reinterpret_cast<const float4*>(rowA + 128 * j));
        }
        if (doB) {
#pragma unroll
            for (int j = 0; j < 4; j++)
                aB[j] = __ldcs(reinterpret_cast<const float4*>(rowB + 128 * j));
        }

        float pA = 0.f, pB = 0.f;
        if (doA) {
#pragma unroll
            for (int j = 0; j < 4; j++) {
                pA = fmaf(aA[j].x, kf[j].x, pA);
                pA = fmaf(aA[j].y, kf[j].y, pA);
                pA = fmaf(aA[j].z, kf[j].z, pA);
                pA = fmaf(aA[j].w, kf[j].w, pA);
            }
        }
        if (doB) {
#pragma unroll
            for (int j = 0; j < 4; j++) {
                pB = fmaf(aB[j].x, kf[j].x, pB);
                pB = fmaf(aB[j].y, kf[j].y, pB);
                pB = fmaf(aB[j].z, kf[j].z, pB);
                pB = fmaf(aB[j].w, kf[j].w, pB);
            }
        }
#pragma unroll
        for (int off = 16; off > 0; off >>= 1) {
            if (doA) pA += __shfl_xor_sync(0xffffffffu, pA, off);
            if (doB) pB += __shfl_xor_sync(0xffffffffu, pB, off);
        }

        if (doA) {
            float mn    = fmaxf(mA, pA);
            float alpha = __expf(mA - mn);   // mA=-inf -> 0
            float w     = __expf(pA - mn);
            sA = sA * alpha + w;
#pragma unroll
            for (int j = 0; j < 4; j++) {
                cA[j].x = fmaf(w, aA[j].x, cA[j].x * alpha);
                cA[j].y = fmaf(w, aA[j].y, cA[j].y * alpha);
                cA[j].z = fmaf(w, aA[j].z, cA[j].z * alpha);
                cA[j].w = fmaf(w, aA[j].w, cA[j].w * alpha);
            }
            mA = mn;
        }
        if (doB) {
            float mn    = fmaxf(mB, pB);
            float alpha = __expf(mB - mn);
            float w     = __expf(pB - mn);
            sB = sB * alpha + w;
#pragma unroll
            for (int j = 0; j < 4; j++) {
                cB[j].x = fmaf(w, aB[j].x, cB[j].x * alpha);
                cB[j].y = fmaf(w, aB[j].y, cB[j].y * alpha);
                cB[j].z = fmaf(w, aB[j].z, cB[j].z * alpha);
                cB[j].w = fmaf(w, aB[j].w, cB[j].w * alpha);
            }
            mB = mn;
        }
    }

    // merge states A and B within the warp (guard all-masked: both -inf)
    float m = fmaxf(mA, mB), s;
    if (m == -INFINITY) {
        s = 0.f;
#pragma unroll
        for (int j = 0; j < 4; j++) cA[j] = make_float4(0.f, 0.f, 0.f, 0.f);
    } else {
        float eA = (mA == -INFINITY) ? 0.f : __expf(mA - m);
        float eB = (mB == -INFINITY) ? 0.f : __expf(mB - m);
        s = sA * eA + sB * eB;
#pragma unroll
        for (int j = 0; j < 4; j++) {
            cA[j].x = cA[j].x * eA + cB[j].x * eB;
            cA[j].y = cA[j].y * eA + cB[j].y * eB;
            cA[j].z = cA[j].z * eA + cB[j].z * eB;
            cA[j].w = cA[j].w * eA + cB[j].w * eB;
        }
    }

    // ---- CTA-level merge of the 4 warp states (smem) ----
    __shared__ float sm_m[WARPS], sm_s[WARPS];
    __shared__ float sm_c[WARPS][D];
    if (lane == 0) { sm_m[warp] = m; sm_s[warp] = s; }
    __syncthreads();
    const float M = fmaxf(fmaxf(sm_m[0], sm_m[1]), fmaxf(sm_m[2], sm_m[3]));
    const float myscale = (m == -INFINITY) ? 0.f : __expf(m - M);
    float* cw = &sm_c[warp][4 * lane];
#pragma unroll
    for (int j = 0; j < 4; j++) {
        float4 v = cA[j];
        v.x *= myscale; v.y *= myscale; v.z *= myscale; v.w *= myscale;
        *reinterpret_cast<float4*>(cw + 128 * j) = v;
    }
    __syncthreads();

    const int pid = blockIdx.x;   // b*NSPLIT + split
    if (threadIdx.x == 0) {
        float st = 0.f;
#pragma unroll
        for (int w = 0; w < WARPS; w++) {
            float sc = (sm_m[w] == -INFINITY) ? 0.f : __expf(sm_m[w] - M);
            st += sm_s[w] * sc;
        }
        g_pm[pid] = M;
        g_ps[pid] = st;
    }
    float* pc = g_pc + (size_t)pid * D;
#pragma unroll
    for (int j = 0; j < 4; j++) {
        int col = threadIdx.x + 128 * j;
        pc[col] = ((sm_c[0][col] + sm_c[1][col]) + (sm_c[2][col] + sm_c[3][col]));
    }
}

// ---------------------------------------------------------------------------
// Kernel 3: combine 32 partials per batch.  256 CTAs (4 per batch), 128
// threads; each thread owns one of its CTA's 128 D-columns.
// ---------------------------------------------------------------------------
__global__ __launch_bounds__(128) void reduce_kernel(float* __restrict__ out) {
    const int b    = blockIdx.x >> 2;
    const int part = blockIdx.x & 3;
    const int tid  = threadIdx.x;

    __shared__ float sc[NPART];
    __shared__ float Msh, Ssh;

    if (tid < NPART) sc[tid] = g_pm[b * NPART + tid];
    __syncthreads();
    if (tid == 0) {
        float mm = -INFINITY;
#pragma unroll
        for (int i = 0; i < NPART; i++) mm = fmaxf(mm, sc[i]);
        Msh = mm;
    }
    __syncthreads();
    if (tid < NPART) {
        float mi = sc[tid];
        sc[tid] = (mi == -INFINITY) ? 0.f : __expf(mi - Msh);
    }
    __syncthreads();
    if (tid == 0) {
        float acc = 0.f;
#pragma unroll
        for (int i = 0; i < NPART; i++) acc += sc[i] * g_ps[b * NPART + i];
        Ssh = acc;
    }
    __syncthreads();

    const int d = part * 128 + tid;
    float acc = 0.f;
    const float* pc = g_pc + (size_t)b * NPART * D + d;
#pragma unroll
    for (int i = 0; i < NPART; i++)
        acc = fmaf(pc[(size_t)i * D], sc[i], acc);
    out[b * D + d] = acc / Ssh;
}

// ---------------------------------------------------------------------------
extern "C" void kernel_launch(void* const* d_in, const int* in_sizes, int n_in,
                              void* d_out, int out_size) {
    const float* q    = (const float*)d_in[0];   // [B, D]
    const float* A    = (const float*)d_in[1];   // [B, T, D]
    const void*  mask = d_in[2];                 // [T, B] bool-ish (dtype sniffed)
    const float* W    = (const float*)d_in[3];   // [D, D]
    const float* bias = (const float*)d_in[4];   // [D]
    float*       out  = (float*)d_out;           // [B, 1, D]

    key_kernel<<<dim3(D / KD, B / KB, KZ), 256>>>(q, W, bias, (const unsigned int*)mask);
    fold_kernel<<<(B * D) / 256, 256>>>();
    partial_kernel<<<B * NSPLIT, WARPS * 32>>>(A, mask);
    reduce_kernel<<<B * 4, 128>>>(out);
}

// round 14
// speedup vs baseline: 1.0188x; 1.0162x over previous
#include <cuda_runtime.h>
#include <math.h>

#define B 64
#define T 4096
#define D 512
#define NSPLIT 32                // CTAs per batch in partial kernel
#define WARPS 4                  // warps per CTA (128 threads)
#define NPART NSPLIT             // ONE partial per CTA (warps merged in smem)
#define ROWS_PER_WARP 32         // (T/NSPLIT)/WARPS

#define KD 32                    // key kernel: d-columns per CTA
#define KB 32                    // key kernel: batches per CTA
#define KZ 16                    // key kernel: split-K factor
#define KSLICE (D / KZ)          // 32 floats per K slice
#define QP4 9                    // smem pitch in float4 (odd -> conflict-free)

// Scratch (static device globals: allocation-free)
__device__ float g_kpart[KZ * B * D];                // 2 MB (split-K partials)
__device__ float g_key[B * D];                       // 128 KB (folded key)
__device__ float g_pm[B * NPART];
__device__ float g_ps[B * NPART];
__device__ float g_pc[(size_t)B * NPART * D];        // 4.2 MB
__device__ int   g_mask_kind;                        // 0=int32, 1=uint8, 2=float32

// ---------------------------------------------------------------------------
// Kernel 1: split-K key GEMM (unchanged from R13).
// ---------------------------------------------------------------------------
__global__ __launch_bounds__(256) void key_kernel(const float* __restrict__ q,
                                                  const float* __restrict__ W,
                                                  const float* __restrict__ bias,
                                                  const unsigned int* __restrict__ mw) {
    if (blockIdx.x == 0 && blockIdx.y == 0 && blockIdx.z == 0) {
        int kind = 0;
        for (int i = threadIdx.x; i < 2048; i += blockDim.x) {
            unsigned int w = mw[i];
            if (w == 0x3f800000u)            kind = 2;                    // float 1.0f
            else if ((w & 0xFFFFFF00u) != 0) kind = kind > 1 ? kind : 1;  // high byte set
        }
        if (kind) atomicMax(&g_mask_kind, kind);   // stays 0 => int32
    }

    __shared__ float4 qs[KB * QP4];

    const int b0 = blockIdx.y * KB;
    const int d0 = blockIdx.x * KD;
    const int k0 = blockIdx.z * KSLICE;

    {
        int row = threadIdx.x >> 3;
        int col = threadIdx.x & 7;
        qs[row * QP4 + col] =
            *reinterpret_cast<const float4*>(q + (size_t)(b0 + row) * D + k0 + 4 * col);
    }
    __syncthreads();

    const int warp = threadIdx.x >> 5;
    const int lane = threadIdx.x & 31;
    const int d    = d0 + warp * 4 + (lane >> 3);
    const int bl   = lane & 7;

    const float4* wrow = reinterpret_cast<const float4*>(W + (size_t)d * D + k0);

    float4 acc[4];
#pragma unroll
    for (int u = 0; u < 4; u++) acc[u] = make_float4(0.f, 0.f, 0.f, 0.f);

#pragma unroll
    for (int j = 0; j < KSLICE / 4; j++) {
        float4 wv = wrow[j];
#pragma unroll
        for (int u = 0; u < 4; u++) {
            float4 qv = qs[(bl + 8 * u) * QP4 + j];
            acc[u].x = fmaf(wv.x, qv.x, acc[u].x);
            acc[u].y = fmaf(wv.y, qv.y, acc[u].y);
            acc[u].z = fmaf(wv.z, qv.z, acc[u].z);
            acc[u].w = fmaf(wv.w, qv.w, acc[u].w);
        }
    }

    const float bd = (blockIdx.z == 0) ? bias[d] : 0.f;
#pragma unroll
    for (int u = 0; u < 4; u++) {
        float r = (acc[u].x + acc[u].y) + (acc[u].z + acc[u].w) + bd;
        g_kpart[blockIdx.z * (B * D) + (size_t)(b0 + bl + 8 * u) * D + d] = r;
    }
}

// ---------------------------------------------------------------------------
// Kernel 1b: fold split-K slices into g_key once (unchanged).
// ---------------------------------------------------------------------------
__global__ __launch_bounds__(256) void fold_kernel() {
    const int i = blockIdx.x * 256 + threadIdx.x;
    float s = 0.f;
#pragma unroll
    for (int z = 0; z < KZ; z++)
        s += g_kpart[z * (B * D) + i];
    g_key[i] = s;
}

// ---------------------------------------------------------------------------
// Kernel 2: per-warp online softmax, REWORKED:
//  * batch-2 single-state update: one rescale per row pair
//      mn = max(m, pA, pB); c = c*alpha + wA*aA + wB*aB  (algebraically exact)
//    -> halves the serial exp-chain, frees 16 registers vs dual-state.
//  * explicit depth-1 software pipeline: pair i+1's guarded LDG.128s issue
//    BEFORE pair i's dot/shuffle/exp chain (load latency covered by one full
//    pair-process window regardless of ptxas scheduling).
//  * buffers zero-initialized once: stale data in masked slots is finite and
//    annihilated by w=0.
// ---------------------------------------------------------------------------
__global__ __launch_bounds__(128) void partial_kernel(const float* __restrict__ A,
                                                      const void* __restrict__ mask_raw) {
    const int b     = blockIdx.x / NSPLIT;
    const int split = blockIdx.x % NSPLIT;
    const int warp  = threadIdx.x >> 5;
    const int lane  = threadIdx.x & 31;
    const int t0    = split * (T / NSPLIT) + warp * ROWS_PER_WARP;

    const size_t midx = (size_t)(t0 + lane) * B + b;
    const int kind = g_mask_kind;
    bool masked;
    if (kind == 1)      masked = ((const unsigned char*)mask_raw)[midx] != 0;
    else if (kind == 0) masked = ((const int*)mask_raw)[midx] != 0;
    else                masked = ((const float*)mask_raw)[midx] != 0.f;
    const unsigned act = ~__ballot_sync(0xffffffffu, masked);   // bit r = row active

    float4 kf[4];
    const float* kb = g_key + b * D + 4 * lane;
#pragma unroll
    for (int j = 0; j < 4; j++)
        kf[j] = *reinterpret_cast<const float4*>(kb + 128 * j);

    float m = -INFINITY, s = 0.f;
    float4 c[4];
#pragma unroll
    for (int j = 0; j < 4; j++) c[j] = make_float4(0.f, 0.f, 0.f, 0.f);

    const float* base = A + ((size_t)b * T + t0) * D + 4 * lane;

    // pipeline buffers (zero-init once; stale finite data is harmless)
    float4 bufA[2][4], bufB[2][4];
#pragma unroll
    for (int j = 0; j < 4; j++) {
        bufA[0][j] = bufA[1][j] = make_float4(0.f, 0.f, 0.f, 0.f);
        bufB[0][j] = bufB[1][j] = make_float4(0.f, 0.f, 0.f, 0.f);
    }

    // prefetch pair 0 into slot 0
    if (act & 1u) {
#pragma unroll
        for (int j = 0; j < 4; j++)
            bufA[0][j] = __ldcs(reinterpret_cast<const float4*>(base + 128 * j));
    }
    if (act & 2u) {
#pragma unroll
        for (int j = 0; j < 4; j++)
            bufB[0][j] = __ldcs(reinterpret_cast<const float4*>(base + D + 128 * j));
    }

#pragma unroll
    for (int i = 0; i < ROWS_PER_WARP / 2; i++) {
        const int rp  = 2 * i;
        const int cur = i & 1;
        const int nxt = cur ^ 1;

        // ---- prefetch pair i+1 (issues before this pair's serial chain) ----
        if (i < ROWS_PER_WARP / 2 - 1) {
            const int rq = rp + 2;
            if ((act >> rq) & 1u) {
                const float* r = base + (size_t)rq * D;
#pragma unroll
                for (int j = 0; j < 4; j++)
                    bufA[nxt][j] = __ldcs(reinterpret_cast<const float4*>(r + 128 * j));
            }
            if ((act >> (rq + 1)) & 1u) {
                const float* r = base + (size_t)(rq + 1) * D;
#pragma unroll
                for (int j = 0; j < 4; j++)
                    bufB[nxt][j] = __ldcs(reinterpret_cast<const float4*>(r + 128 * j));
            }
        }

        // ---- process pair i ----
        const bool doA = (act >> rp) & 1u;        // warp-uniform
        const bool doB = (act >> (rp + 1)) & 1u;  // warp-uniform
        if (doA || doB) {
            float pA = 0.f, pB = 0.f;
            if (doA) {
#pragma unroll
                for (int j = 0; j < 4; j++) {
                    pA = fmaf(bufA[cur][j].x, kf[j].x, pA);
                    pA = fmaf(bufA[cur][j].y, kf[j].y, pA);
                    pA = fmaf(bufA[cur][j].z, kf[j].z, pA);
                    pA = fmaf(bufA[cur][j].w, kf[j].w, pA);
                }
            }
            if (doB) {
#pragma unroll
                for (int j = 0; j < 4; j++) {
                    pB = fmaf(bufB[cur][j].x, kf[j].x, pB);
                    pB = fmaf(bufB[cur][j].y, kf[j].y, pB);
                    pB = fmaf(bufB[cur][j].z, kf[j].z, pB);
                    pB = fmaf(bufB[cur][j].w, kf[j].w, pB);
                }
            }
#pragma unroll
            for (int off = 16; off > 0; off >>= 1) {
                if (doA) pA += __shfl_xor_sync(0xffffffffu, pA, off);
                if (doB) pB += __shfl_xor_sync(0xffffffffu, pB, off);
            }

            // batch-2 single-state online softmax update
            float mn = m;
            if (doA) mn = fmaxf(mn, pA);
            if (doB) mn = fmaxf(mn, pB);
            const float alpha = __expf(m - mn);              // m=-inf -> 0
            const float wA = doA ? __expf(pA - mn) : 0.f;
            const float wB = doB ? __expf(pB - mn) : 0.f;
            s = s * alpha + wA + wB;
#pragma unroll
            for (int j = 0; j < 4; j++) {
                c[j].x = fmaf(wB, bufB[cur][j].x, fmaf(wA, bufA[cur][j].x, c[j].x * alpha));
                c[j].y = fmaf(wB, bufB[cur][j].y, fmaf(wA, bufA[cur][j].y, c[j].y * alpha));
                c[j].z = fmaf(wB, bufB[cur][j].z, fmaf(wA, bufA[cur][j].z, c[j].z * alpha));
                c[j].w = fmaf(wB, bufB[cur][j].w, fmaf(wA, bufA[cur][j].w, c[j].w * alpha));
            }
            m = mn;
        }
    }

    // ---- CTA-level merge of the 4 warp states (smem) ----
    __shared__ float sm_m[WARPS], sm_s[WARPS];
    __shared__ float sm_c[WARPS][D];
    if (lane == 0) { sm_m[warp] = m; sm_s[warp] = s; }
    __syncthreads();
    const float M = fmaxf(fmaxf(sm_m[0], sm_m[1]), fmaxf(sm_m[2], sm_m[3]));
    const float myscale = (m == -INFINITY) ? 0.f : __expf(m - M);
    float* cw = &sm_c[warp][4 * lane];
#pragma unroll
    for (int j = 0; j < 4; j++) {
        float4 v = c[j];
        v.x *= myscale; v.y *= myscale; v.z *= myscale; v.w *= myscale;
        *reinterpret_cast<float4*>(cw + 128 * j) = v;
    }
    __syncthreads();

    const int pid = blockIdx.x;   // b*NSPLIT + split
    if (threadIdx.x == 0) {
        float st = 0.f;
#pragma unroll
        for (int w = 0; w < WARPS; w++) {
            float sc = (sm_m[w] == -INFINITY) ? 0.f : __expf(sm_m[w] - M);
            st += sm_s[w] * sc;
        }
        g_pm[pid] = M;
        g_ps[pid] = st;
    }
    float* pc = g_pc + (size_t)pid * D;
#pragma unroll
    for (int j = 0; j < 4; j++) {
        int col = threadIdx.x + 128 * j;
        pc[col] = ((sm_c[0][col] + sm_c[1][col]) + (sm_c[2][col] + sm_c[3][col]));
    }
}

// ---------------------------------------------------------------------------
// Kernel 3: combine 32 partials per batch.  REWORKED: 512 CTAs (8 per batch)
// x 64 threads; warp 0 computes the scale vector and total sum via shuffle
// reductions (no serial tid==0 loops). Each thread owns one D-column.
// ---------------------------------------------------------------------------
__global__ __launch_bounds__(64) void reduce_kernel(float* __restrict__ out) {
    const int b    = blockIdx.x >> 3;
    const int part = blockIdx.x & 7;
    const int tid  = threadIdx.x;

    __shared__ float sc[NPART];
    __shared__ float Ssh;

    if (tid < 32) {
        const float mi = g_pm[b * NPART + tid];
        float mm = mi;
#pragma unroll
        for (int off = 16; off > 0; off >>= 1)
            mm = fmaxf(mm, __shfl_xor_sync(0xffffffffu, mm, off));
        const float scale = (mi == -INFINITY) ? 0.f : __expf(mi - mm);
        sc[tid] = scale;
        float sv = scale * g_ps[b * NPART + tid];
#pragma unroll
        for (int off = 16; off > 0; off >>= 1)
            sv += __shfl_xor_sync(0xffffffffu, sv, off);
        if (tid == 0) Ssh = sv;
    }
    __syncthreads();

    const int d = part * 64 + tid;
    float acc = 0.f;
    const float* pc = g_pc + (size_t)b * NPART * D + d;
#pragma unroll
    for (int i = 0; i < NPART; i++)
        acc = fmaf(pc[(size_t)i * D], sc[i], acc);
    out[b * D + d] = acc / Ssh;
}

// ---------------------------------------------------------------------------
extern "C" void kernel_launch(void* const* d_in, const int* in_sizes, int n_in,
                              void* d_out, int out_size) {
    const float* q    = (const float*)d_in[0];   // [B, D]
    const float* A    = (const float*)d_in[1];   // [B, T, D]
    const void*  mask = d_in[2];                 // [T, B] bool-ish (dtype sniffed)
    const float* W    = (const float*)d_in[3];   // [D, D]
    const float* bias = (const float*)d_in[4];   // [D]
    float*       out  = (float*)d_out;           // [B, 1, D]

    key_kernel<<<dim3(D / KD, B / KB, KZ), 256>>>(q, W, bias, (const unsigned int*)mask);
    fold_kernel<<<(B * D) / 256, 256>>>();
    partial_kernel<<<B * NSPLIT, WARPS * 32>>>(A, mask);
    reduce_kernel<<<B * 8, 64>>>(out);
}